// round 14
// baseline (speedup 1.0000x reference)
#include <cuda_runtime.h>
#include <cstdint>

#define BB   32
#define SS   1024
#define HH   256
#define G4   1024   // 4*H
#define H2   512    // 2*H

typedef unsigned long long ull;

// ---------------- f32x2 helpers (Blackwell packed fp32, 2 MAC/inst) -------
__device__ __forceinline__ ull ffma2(ull a, ull b, ull c)
{
    ull d;
    asm("fma.rn.f32x2 %0, %1, %2, %3;" : "=l"(d) : "l"(a), "l"(b), "l"(c));
    return d;
}
__device__ __forceinline__ ull pack_dup(float a)
{
    ull d;
    unsigned u = __float_as_uint(a);
    asm("mov.b64 %0, {%1, %1};" : "=l"(d) : "r"(u));
    return d;
}
__device__ __forceinline__ float2 unpack2(ull v)
{
    unsigned lo, hi;
    asm("mov.b64 {%0, %1}, %2;" : "=r"(lo), "=r"(hi) : "l"(v));
    return make_float2(__uint_as_float(lo), __uint_as_float(hi));
}

// ---------------- scoped release/acquire flag ops -------------------------
__device__ __forceinline__ void st_release_gpu(int* p, int v)
{
    asm volatile("st.release.gpu.global.u32 [%0], %1;" :: "l"(p), "r"(v) : "memory");
}
__device__ __forceinline__ int ld_acquire_gpu(const int* p)
{
    int v;
    asm volatile("ld.acquire.gpu.global.u32 %0, [%1];" : "=r"(v) : "l"(p) : "memory");
    return v;
}

// ------------------------- scratch (device globals; no allocs) -------------
// gates in recurrence layout: [s][cb(64)][b(32)][16]  (16 = gate*4+u)
__device__ float g_gates_f[(size_t)SS * BB * G4];   // 128 MB
__device__ float g_gates_b[(size_t)SS * BB * G4];   // 128 MB
__device__ float g_xout  [(size_t)SS * BB * H2];    //  64 MB (layer-0 output)
// replicated flags: [layer][dir][consumer(64)][producer(64)]
__device__ int   g_flags [2 * 2 * 64 * 64];
// h exchange: [dir][parity][b(32)][64] float4  (plain [b][k] row-major)
__device__ float g_hx    [2 * 2 * 32 * 256];

// --------------------------------------------------------------------------
__global__ void zero_flags_k()
{
    int i = blockIdx.x * blockDim.x + threadIdx.x;
    if (i < 2 * 2 * 64 * 64) g_flags[i] = 0;
}

// --------------------------------------------------------------------------
// x-GEMM (unchanged — measured 65.9% fma): tiles 128x128, f32x2, pipelined
// LDG; blockIdx.z selects fwd/bwd weight set + output buffer.
__global__ void __launch_bounds__(256) gates_gemm(
    const float* __restrict__ A,
    const float* __restrict__ Wf, const float* __restrict__ bihf, const float* __restrict__ bhhf,
    const float* __restrict__ Wb, const float* __restrict__ bihb, const float* __restrict__ bhhb,
    float* __restrict__ Cf, float* __restrict__ Cb,
    int K, int a_mode)
{
    __shared__ __align__(16) float As[16][132];
    __shared__ __align__(16) float Bs[16][132];

    const int z = blockIdx.z;
    const float* W   = z ? Wb   : Wf;
    const float* bih = z ? bihb : bihf;
    const float* bhh = z ? bhhb : bhhf;
    float* C2        = z ? Cb   : Cf;

    const int tid = threadIdx.x;
    const int tx = tid & 15;
    const int ty = tid >> 4;
    const int m0 = blockIdx.y * 128;
    const int n0 = blockIdx.x * 128;

    const int lr = tid >> 2;
    const int lc = (tid & 3) << 2;

    const float* arow0;
    const float* arow1;
    {
        int m  = m0 + lr;
        int m2 = m + 64;
        if (a_mode == 0) {
            int s = m >> 5, b = m & 31;
            arow0 = A + ((size_t)b * SS + s) * K;
            s = m2 >> 5; b = m2 & 31;
            arow1 = A + ((size_t)b * SS + s) * K;
        } else {
            arow0 = A + (size_t)m  * K;
            arow1 = A + (size_t)m2 * K;
        }
    }
    const float* wrow0 = W + (size_t)(n0 + lr)      * K;
    const float* wrow1 = W + (size_t)(n0 + lr + 64) * K;

    ull accp[8][4];
#pragma unroll
    for (int i = 0; i < 8; ++i)
#pragma unroll
        for (int j = 0; j < 4; ++j) accp[i][j] = 0ull;

    const int KT = K >> 4;

    float4 a0 = *(const float4*)(arow0 + lc);
    float4 a1 = *(const float4*)(arow1 + lc);
    float4 b0 = *(const float4*)(wrow0 + lc);
    float4 b1 = *(const float4*)(wrow1 + lc);

    for (int kt = 0; kt < KT; ++kt) {
        __syncthreads();
        As[lc + 0][lr] = a0.x; As[lc + 1][lr] = a0.y; As[lc + 2][lr] = a0.z; As[lc + 3][lr] = a0.w;
        As[lc + 0][lr + 64] = a1.x; As[lc + 1][lr + 64] = a1.y; As[lc + 2][lr + 64] = a1.z; As[lc + 3][lr + 64] = a1.w;
        Bs[lc + 0][lr] = b0.x; Bs[lc + 1][lr] = b0.y; Bs[lc + 2][lr] = b0.z; Bs[lc + 3][lr] = b0.w;
        Bs[lc + 0][lr + 64] = b1.x; Bs[lc + 1][lr + 64] = b1.y; Bs[lc + 2][lr + 64] = b1.z; Bs[lc + 3][lr + 64] = b1.w;
        __syncthreads();
        if (kt + 1 < KT) {
            int k0 = (kt + 1) << 4;
            a0 = *(const float4*)(arow0 + k0 + lc);
            a1 = *(const float4*)(arow1 + k0 + lc);
            b0 = *(const float4*)(wrow0 + k0 + lc);
            b1 = *(const float4*)(wrow1 + k0 + lc);
        }
#pragma unroll
        for (int k = 0; k < 16; ++k) {
            float4 af0 = *(const float4*)&As[k][ty * 4];
            float4 af1 = *(const float4*)&As[k][64 + ty * 4];
            ulonglong2 bv0 = *(const ulonglong2*)&Bs[k][tx * 4];
            ulonglong2 bv1 = *(const ulonglong2*)&Bs[k][64 + tx * 4];
            ull bp[4] = {bv0.x, bv0.y, bv1.x, bv1.y};
            float a_[8] = {af0.x, af0.y, af0.z, af0.w, af1.x, af1.y, af1.z, af1.w};
#pragma unroll
            for (int i = 0; i < 8; ++i) {
                ull ad = pack_dup(a_[i]);
#pragma unroll
                for (int j = 0; j < 4; ++j)
                    accp[i][j] = ffma2(ad, bp[j], accp[i][j]);
            }
        }
    }

#pragma unroll
    for (int qi = 0; qi < 2; ++qi) {
#pragma unroll
        for (int i = 0; i < 4; ++i) {
            int m = m0 + qi * 64 + ty * 4 + i;
            int s = m >> 5, b = m & 31;
#pragma unroll
            for (int qj = 0; qj < 2; ++qj) {
                int n = n0 + qj * 64 + tx * 4;
                float2 p0 = unpack2(accp[qi * 4 + i][qj * 2 + 0]);
                float2 p1 = unpack2(accp[qi * 4 + i][qj * 2 + 1]);
                float4 v;
                v.x = p0.x + bih[n + 0] + bhh[n + 0];
                v.y = p0.y + bih[n + 1] + bhh[n + 1];
                v.z = p1.x + bih[n + 2] + bhh[n + 2];
                v.w = p1.y + bih[n + 3] + bhh[n + 3];
                int g  = n >> 8;
                int ub = (n & 255) >> 2;
                *(float4*)&C2[(((size_t)s * 64 + ub) * 32 + b) * 16 + g * 4] = v;
            }
        }
    }
}

// --------------------------------------------------------------------------
// Recurrence v6: R12 GEMM core + cell + release, but warp-local sync:
//  - each warp's GEMM reads ONLY its own 4 batch rows of h -> staging is
//    warp-private: lane polls its 2 producers (pure spin, ld.acquire),
//    stages its 8 coalesced float4, __syncwarp, GEMM. NO CTA barrier
//    before the GEMM (two barriers deleted vs R12).
//  - one CTA barrier remains (sh_g -> cell), plus the pre-release barrier.
__device__ __forceinline__ float sigm_f(float x)
{
    float e = __expf(-x);
    return __fdividef(1.f, 1.f + e);
}
__device__ __forceinline__ float tanh_f(float x)
{
    float xc = fminf(fmaxf(x, -30.f), 30.f);
    float e = __expf(-2.f * xc);
    return __fdividef(1.f - e, 1.f + e);
}

__global__ void __launch_bounds__(256) lstm_recur(
    const float* __restrict__ gatesF2, const float* __restrict__ gatesB2,
    const float* __restrict__ WhhF, const float* __restrict__ WhhB,
    const float* __restrict__ mask,
    float* __restrict__ xout,
    float* __restrict__ hn_out, float* __restrict__ cn_out,
    int* __restrict__ flags,        // [dir][cons64][prod64]
    float* __restrict__ hx,         // [dir][parity][32][64] float4
    int out_bs)
{
    __shared__ __align__(16) float4 sh_h4[32 * 66];   // swizzled h, pad 66
    __shared__ __align__(16) float  sh_g[32 * 20];    // gates, stride 20

    const int tid  = threadIdx.x;
    const int dir  = blockIdx.x >> 6;
    const int cb   = blockIdx.x & 63;
    const int u0   = cb * 4;
    const int bg   = tid >> 5;        // warp: batch group (8)
    const int lane = tid & 31;
    const int rg   = lane >> 3;       // gate (4)
    const int ks   = lane & 7;        // k slice (8): k = ks*32 .. +31

    const float* gates2 = dir ? gatesB2 : gatesF2;
    const float* Whh    = dir ? WhhB    : WhhF;
    int* fl_my   = flags + (dir * 64 + cb) * 64;
    int* fl_base = flags + dir * 64 * 64;

    // ---- one-time: W slice (rows rg*4+r = gate rg, unit r; k in slice) ----
    ull w[4][16];
#pragma unroll
    for (int r = 0; r < 4; ++r) {
        const float* wr = Whh + (size_t)(rg * HH + u0 + r) * HH + ks * 32;
#pragma unroll
        for (int f = 0; f < 8; ++f) {
            ulonglong2 v = *(const ulonglong2*)(wr + f * 4);
            w[r][f * 2 + 0] = v.x;
            w[r][f * 2 + 1] = v.y;
        }
    }

    float4 c4 = make_float4(0.f, 0.f, 0.f, 0.f);   // cell state (tid<32)

    for (int t = 0; t < SS; ++t) {
        const int s = dir ? (SS - 1 - t) : t;

        // cell-warp early loads (independent of everything below)
        float4 gxa, gxb, gxc, gxd;
        float mt = 0.f;
        if (tid < 32) {
            const float* gp = gates2 + (((size_t)s * 64 + cb) * 32 + tid) * 16;
            gxa = *(const float4*)(gp + 0);
            gxb = *(const float4*)(gp + 4);
            gxc = *(const float4*)(gp + 8);
            gxd = *(const float4*)(gp + 12);
            mt  = __ldg(mask + tid * SS + s);
        }

        if (t > 0) {
            // ---- per-lane wait on MY 2 producers (pure spin) ----
            // lane stages float4 q = jj*32+lane of this warp's 4KB block:
            // k4 = q&63 in {lane, lane+32} -> producers cb' = lane, lane+32.
            {
                const int* f0 = fl_my + lane;
                const int* f1 = fl_my + lane + 32;
                while (ld_acquire_gpu(f0) < t) { }
                while (ld_acquire_gpu(f1) < t) { }
            }
            // ---- warp-private staging of its 4 batch rows (coalesced) ----
            const float4* src = (const float4*)hx
                + ((size_t)dir * 2 + ((t - 1) & 1)) * 2048;
            const float4* wsrc = src + bg * 4 * 64;   // rows bg*4..bg*4+3
#pragma unroll
            for (int jj = 0; jj < 8; ++jj) {
                int q  = jj * 32 + lane;
                int b  = bg * 4 + (q >> 6);
                int k4 = q & 63;
                int kss = k4 >> 3, j = k4 & 7;
                float4 v = __ldcg(wsrc + q);
                sh_h4[b * 66 + kss * 8 + ((j + kss) & 7)] = v;
            }
            __syncwarp();

            // ---- hGEMM: acc[4b][4r] over k-slice, packed pairs ----
            ull acc[4][4];
#pragma unroll
            for (int i = 0; i < 4; ++i)
#pragma unroll
                for (int r = 0; r < 4; ++r) acc[i][r] = 0ull;

#pragma unroll
            for (int k2 = 0; k2 < 16; ++k2) {
                const int co = (((k2 >> 1) + ks) & 7) * 2 + (k2 & 1);
#pragma unroll
                for (int i = 0; i < 4; ++i) {
                    const ull* hp = (const ull*)&sh_h4[(bg * 4 + i) * 66 + ks * 8];
                    ull h = hp[co];
#pragma unroll
                    for (int r = 0; r < 4; ++r)
                        acc[i][r] = ffma2(h, w[r][k2], acc[i][r]);
                }
            }

            // horizontal add -> floats, then 3-round float butterfly over ks
            float g[4][4];
#pragma unroll
            for (int i = 0; i < 4; ++i)
#pragma unroll
                for (int r = 0; r < 4; ++r) {
                    float2 u = unpack2(acc[i][r]);
                    g[i][r] = u.x + u.y;
                }
#pragma unroll
            for (int d = 1; d < 8; d <<= 1) {
#pragma unroll
                for (int i = 0; i < 4; ++i)
#pragma unroll
                    for (int r = 0; r < 4; ++r)
                        g[i][r] += __shfl_xor_sync(0xffffffffu, g[i][r], d);
            }
            if (ks == 0) {
#pragma unroll
                for (int i = 0; i < 4; ++i)
#pragma unroll
                    for (int r = 0; r < 4; ++r)
                        sh_g[(bg * 4 + i) * 20 + rg * 4 + r] = g[i][r];
            }
        } else {
            if (tid < 32) {
#pragma unroll
                for (int r = 0; r < 16; ++r) sh_g[tid * 20 + r] = 0.f;
            }
        }
        __syncthreads();

        // ---- cell (32 threads, one batch each, 4 units) ----
        if (tid < 32) {
            const float* gh = &sh_g[tid * 20];
            float4 hn4, cn4;
            float* hnp = &hn4.x;
            float* cnp = &cn4.x;
            float* csp = &c4.x;
            const float* gxi = &gxa.x;
            const float* gxf = &gxb.x;
            const float* gxg = &gxc.x;
            const float* gxo = &gxd.x;
#pragma unroll
            for (int u = 0; u < 4; ++u) {
                float ig = sigm_f(gxi[u] + gh[0  + u]);
                float fg = sigm_f(gxf[u] + gh[4  + u]);
                float gv = tanh_f(gxg[u] + gh[8  + u]);
                float og = sigm_f(gxo[u] + gh[12 + u]);
                float cn = fg * csp[u] + ig * gv;
                float hn = og * tanh_f(cn);
                hn *= mt;            // + h0*(1-mt), h0 == 0
                cn *= mt;            // + c0*(1-mt), c0 == 0
                csp[u] = cn;
                hnp[u] = hn;
                cnp[u] = cn;
            }
            // exchange buffer (critical path): [b][k] float4 index b*64+cb
            ((float4*)hx)[((size_t)dir * 2 + (t & 1)) * 2048 + tid * 64 + cb] = hn4;
            // layer output (off critical path)
            size_t orow = out_bs ? ((size_t)tid * SS + s)
                                 : ((size_t)s * BB + tid);
            *(float4*)&xout[orow * H2 + dir * HH + u0] = hn4;
            if (t == SS - 1) {
                *(float4*)&hn_out[tid * H2 + dir * HH + u0] = hn4;
                *(float4*)&cn_out[tid * H2 + dir * HH + u0] = cn4;
            }
        }
        __syncthreads();   // h stores happen-before the releases
        if (tid < 64) {
            st_release_gpu(fl_base + tid * 64 + cb, t + 1);
        }
    }
}

// --------------------------------------------------------------------------
extern "C" void kernel_launch(void* const* d_in, const int* in_sizes, int n_in,
                              void* d_out, int out_size)
{
    const float* inputs  = (const float*)d_in[0];
    const float* mask    = (const float*)d_in[1];
    const float* l0f_Wih = (const float*)d_in[2];
    const float* l0f_Whh = (const float*)d_in[3];
    const float* l0f_bih = (const float*)d_in[4];
    const float* l0f_bhh = (const float*)d_in[5];
    const float* l0b_Wih = (const float*)d_in[6];
    const float* l0b_Whh = (const float*)d_in[7];
    const float* l0b_bih = (const float*)d_in[8];
    const float* l0b_bhh = (const float*)d_in[9];
    const float* l1f_Wih = (const float*)d_in[10];
    const float* l1f_Whh = (const float*)d_in[11];
    const float* l1f_bih = (const float*)d_in[12];
    const float* l1f_bhh = (const float*)d_in[13];
    const float* l1b_Wih = (const float*)d_in[14];
    const float* l1b_Whh = (const float*)d_in[15];
    const float* l1b_bih = (const float*)d_in[16];
    const float* l1b_bhh = (const float*)d_in[17];
    float* out = (float*)d_out;

    float *p_gf, *p_gb, *p_x, *p_hx;
    int *p_fl;
    cudaGetSymbolAddress((void**)&p_gf, g_gates_f);
    cudaGetSymbolAddress((void**)&p_gb, g_gates_b);
    cudaGetSymbolAddress((void**)&p_x,  g_xout);
    cudaGetSymbolAddress((void**)&p_fl, g_flags);
    cudaGetSymbolAddress((void**)&p_hx, g_hx);

    const size_t HN_OFF = (size_t)BB * SS * H2;       // 16777216
    const size_t CN_OFF = HN_OFF + 2 * (size_t)BB * H2;
    float* hn0 = out + HN_OFF;
    float* hn1 = out + HN_OFF + (size_t)BB * H2;
    float* cn0 = out + CN_OFF;
    float* cn1 = out + CN_OFF + (size_t)BB * H2;

    zero_flags_k<<<64, 256>>>();

    dim3 ggrid(G4 / 128, (SS * BB) / 128, 2);   // (8, 256, 2) fwd+bwd merged

    // ---- layer 0 : recurrence output in [S,B,2H] scratch ----
    gates_gemm<<<ggrid, 256>>>(inputs,
                               l0f_Wih, l0f_bih, l0f_bhh,
                               l0b_Wih, l0b_bih, l0b_bhh,
                               p_gf, p_gb, 256, 0);
    lstm_recur<<<128, 256>>>(p_gf, p_gb, l0f_Whh, l0b_Whh, mask,
                             p_x, hn0, cn0, p_fl, p_hx, 0);

    // ---- layer 1 : recurrence writes final [B,S,2H] output directly ----
    gates_gemm<<<ggrid, 256>>>(p_x,
                               l1f_Wih, l1f_bih, l1f_bhh,
                               l1b_Wih, l1b_bih, l1b_bhh,
                               p_gf, p_gb, 512, 1);
    lstm_recur<<<128, 256>>>(p_gf, p_gb, l1f_Whh, l1b_Whh, mask,
                             out, hn1, cn1, p_fl + 2 * 64 * 64, p_hx, 1);
}

// round 15
// speedup vs baseline: 1.3207x; 1.3207x over previous
#include <cuda_runtime.h>
#include <cstdint>

#define BB   32
#define SS   1024
#define HH   256
#define G4   1024   // 4*H
#define H2   512    // 2*H

typedef unsigned long long ull;

// ---------------- f32x2 helpers (Blackwell packed fp32, 2 MAC/inst) -------
__device__ __forceinline__ ull ffma2(ull a, ull b, ull c)
{
    ull d;
    asm("fma.rn.f32x2 %0, %1, %2, %3;" : "=l"(d) : "l"(a), "l"(b), "l"(c));
    return d;
}
__device__ __forceinline__ ull pack_dup(float a)
{
    ull d;
    unsigned u = __float_as_uint(a);
    asm("mov.b64 %0, {%1, %1};" : "=l"(d) : "r"(u));
    return d;
}
__device__ __forceinline__ float2 unpack2(ull v)
{
    unsigned lo, hi;
    asm("mov.b64 {%0, %1}, %2;" : "=r"(lo), "=r"(hi) : "l"(v));
    return make_float2(__uint_as_float(lo), __uint_as_float(hi));
}

// ---------------- scoped release/acquire flag ops -------------------------
__device__ __forceinline__ void st_release_gpu(int* p, int v)
{
    asm volatile("st.release.gpu.global.u32 [%0], %1;" :: "l"(p), "r"(v) : "memory");
}
__device__ __forceinline__ int ld_acquire_gpu(const int* p)
{
    int v;
    asm volatile("ld.acquire.gpu.global.u32 %0, [%1];" : "=r"(v) : "l"(p) : "memory");
    return v;
}

// ------------------------- scratch (device globals; no allocs) -------------
// gates in recurrence layout: [s][cb(64)][b(32)][16]  (16 = gate*4+u)
__device__ float g_gates_f[(size_t)SS * BB * G4];   // 128 MB
__device__ float g_gates_b[(size_t)SS * BB * G4];   // 128 MB
__device__ float g_xout  [(size_t)SS * BB * H2];    //  64 MB (layer-0 output)
// replicated flags: [layer][dir][consumer(64)][producer(64)]
__device__ int   g_flags [2 * 2 * 64 * 64];
// h exchange: [dir][parity][b(32)][64] float4  (plain [b][k] row-major)
__device__ float g_hx    [2 * 2 * 32 * 256];

// --------------------------------------------------------------------------
__global__ void zero_flags_k()
{
    int i = blockIdx.x * blockDim.x + threadIdx.x;
    if (i < 2 * 2 * 64 * 64) g_flags[i] = 0;
}

// --------------------------------------------------------------------------
// x-GEMM: tiles 128x128, k-tile 16, f32x2, DOUBLE-BUFFERED smem (one
// __syncthreads per k-tile instead of two). blockIdx.z selects fwd/bwd.
__global__ void __launch_bounds__(256) gates_gemm(
    const float* __restrict__ A,
    const float* __restrict__ Wf, const float* __restrict__ bihf, const float* __restrict__ bhhf,
    const float* __restrict__ Wb, const float* __restrict__ bihb, const float* __restrict__ bhhb,
    float* __restrict__ Cf, float* __restrict__ Cb,
    int K, int a_mode)
{
    __shared__ __align__(16) float As[2][16][132];
    __shared__ __align__(16) float Bs[2][16][132];

    const int z = blockIdx.z;
    const float* W   = z ? Wb   : Wf;
    const float* bih = z ? bihb : bihf;
    const float* bhh = z ? bhhb : bhhf;
    float* C2        = z ? Cb   : Cf;

    const int tid = threadIdx.x;
    const int tx = tid & 15;
    const int ty = tid >> 4;
    const int m0 = blockIdx.y * 128;
    const int n0 = blockIdx.x * 128;

    const int lr = tid >> 2;
    const int lc = (tid & 3) << 2;

    const float* arow0;
    const float* arow1;
    {
        int m  = m0 + lr;
        int m2 = m + 64;
        if (a_mode == 0) {
            int s = m >> 5, b = m & 31;
            arow0 = A + ((size_t)b * SS + s) * K;
            s = m2 >> 5; b = m2 & 31;
            arow1 = A + ((size_t)b * SS + s) * K;
        } else {
            arow0 = A + (size_t)m  * K;
            arow1 = A + (size_t)m2 * K;
        }
    }
    const float* wrow0 = W + (size_t)(n0 + lr)      * K;
    const float* wrow1 = W + (size_t)(n0 + lr + 64) * K;

    ull accp[8][4];
#pragma unroll
    for (int i = 0; i < 8; ++i)
#pragma unroll
        for (int j = 0; j < 4; ++j) accp[i][j] = 0ull;

    const int KT = K >> 4;

    float4 a0 = *(const float4*)(arow0 + lc);
    float4 a1 = *(const float4*)(arow1 + lc);
    float4 b0 = *(const float4*)(wrow0 + lc);
    float4 b1 = *(const float4*)(wrow1 + lc);

    for (int kt = 0; kt < KT; ++kt) {
        const int bs = kt & 1;
        As[bs][lc + 0][lr] = a0.x; As[bs][lc + 1][lr] = a0.y;
        As[bs][lc + 2][lr] = a0.z; As[bs][lc + 3][lr] = a0.w;
        As[bs][lc + 0][lr + 64] = a1.x; As[bs][lc + 1][lr + 64] = a1.y;
        As[bs][lc + 2][lr + 64] = a1.z; As[bs][lc + 3][lr + 64] = a1.w;
        Bs[bs][lc + 0][lr] = b0.x; Bs[bs][lc + 1][lr] = b0.y;
        Bs[bs][lc + 2][lr] = b0.z; Bs[bs][lc + 3][lr] = b0.w;
        Bs[bs][lc + 0][lr + 64] = b1.x; Bs[bs][lc + 1][lr + 64] = b1.y;
        Bs[bs][lc + 2][lr + 64] = b1.z; Bs[bs][lc + 3][lr + 64] = b1.w;
        __syncthreads();
        if (kt + 1 < KT) {            // prefetch next tile during compute
            int k0 = (kt + 1) << 4;
            a0 = *(const float4*)(arow0 + k0 + lc);
            a1 = *(const float4*)(arow1 + k0 + lc);
            b0 = *(const float4*)(wrow0 + k0 + lc);
            b1 = *(const float4*)(wrow1 + k0 + lc);
        }
#pragma unroll
        for (int k = 0; k < 16; ++k) {
            float4 af0 = *(const float4*)&As[bs][k][ty * 4];
            float4 af1 = *(const float4*)&As[bs][k][64 + ty * 4];
            ulonglong2 bv0 = *(const ulonglong2*)&Bs[bs][k][tx * 4];
            ulonglong2 bv1 = *(const ulonglong2*)&Bs[bs][k][64 + tx * 4];
            ull bp[4] = {bv0.x, bv0.y, bv1.x, bv1.y};
            float a_[8] = {af0.x, af0.y, af0.z, af0.w, af1.x, af1.y, af1.z, af1.w};
#pragma unroll
            for (int i = 0; i < 8; ++i) {
                ull ad = pack_dup(a_[i]);
#pragma unroll
                for (int j = 0; j < 4; ++j)
                    accp[i][j] = ffma2(ad, bp[j], accp[i][j]);
            }
        }
        // no second barrier: next iter stores into buf^1; the loop-top sync
        // of iter kt+1 orders those stores against everyone's compute(kt).
    }

#pragma unroll
    for (int qi = 0; qi < 2; ++qi) {
#pragma unroll
        for (int i = 0; i < 4; ++i) {
            int m = m0 + qi * 64 + ty * 4 + i;
            int s = m >> 5, b = m & 31;
#pragma unroll
            for (int qj = 0; qj < 2; ++qj) {
                int n = n0 + qj * 64 + tx * 4;
                float2 p0 = unpack2(accp[qi * 4 + i][qj * 2 + 0]);
                float2 p1 = unpack2(accp[qi * 4 + i][qj * 2 + 1]);
                float4 v;
                v.x = p0.x + bih[n + 0] + bhh[n + 0];
                v.y = p0.y + bih[n + 1] + bhh[n + 1];
                v.z = p1.x + bih[n + 2] + bhh[n + 2];
                v.w = p1.y + bih[n + 3] + bhh[n + 3];
                int g  = n >> 8;
                int ub = (n & 255) >> 2;
                *(float4*)&C2[(((size_t)s * 64 + ub) * 32 + b) * 16 + g * 4] = v;
            }
        }
    }
}

// --------------------------------------------------------------------------
// Recurrence: R12 structure verbatim (best measured), two micro-fixes only:
//  - pure-spin poll (no __nanosleep) — 64 pollers/CTA unchanged
//  - butterfly reduce on 16 floats (48 SHFL) instead of 16 packed u64 (96)
__device__ __forceinline__ float sigm_f(float x)
{
    float e = __expf(-x);
    return __fdividef(1.f, 1.f + e);
}
__device__ __forceinline__ float tanh_f(float x)
{
    float xc = fminf(fmaxf(x, -30.f), 30.f);
    float e = __expf(-2.f * xc);
    return __fdividef(1.f - e, 1.f + e);
}

__global__ void __launch_bounds__(256) lstm_recur(
    const float* __restrict__ gatesF2, const float* __restrict__ gatesB2,
    const float* __restrict__ WhhF, const float* __restrict__ WhhB,
    const float* __restrict__ mask,
    float* __restrict__ xout,
    float* __restrict__ hn_out, float* __restrict__ cn_out,
    int* __restrict__ flags,        // [dir][cons64][prod64]
    float* __restrict__ hx,         // [dir][parity][32][64] float4
    int out_bs)
{
    __shared__ __align__(16) float4 sh_h4[32 * 66];   // swizzled h, pad 66
    __shared__ __align__(16) float  sh_g[32 * 20];    // gates, stride 20

    const int tid  = threadIdx.x;
    const int dir  = blockIdx.x >> 6;
    const int cb   = blockIdx.x & 63;
    const int u0   = cb * 4;
    const int bg   = tid >> 5;        // warp: batch group (8)
    const int lane = tid & 31;
    const int rg   = lane >> 3;       // gate (4)
    const int ks   = lane & 7;        // k slice (8): k = ks*32 .. +31

    const float* gates2 = dir ? gatesB2 : gatesF2;
    const float* Whh    = dir ? WhhB    : WhhF;
    int* fl_my   = flags + (dir * 64 + cb) * 64;
    int* fl_base = flags + dir * 64 * 64;

    // ---- one-time: W slice (rows rg*4+r = gate rg, unit r; k in slice) ----
    ull w[4][16];
#pragma unroll
    for (int r = 0; r < 4; ++r) {
        const float* wr = Whh + (size_t)(rg * HH + u0 + r) * HH + ks * 32;
#pragma unroll
        for (int f = 0; f < 8; ++f) {
            ulonglong2 v = *(const ulonglong2*)(wr + f * 4);
            w[r][f * 2 + 0] = v.x;
            w[r][f * 2 + 1] = v.y;
        }
    }

    float4 c4 = make_float4(0.f, 0.f, 0.f, 0.f);   // cell state (tid<32)

    for (int t = 0; t < SS; ++t) {
        const int s = dir ? (SS - 1 - t) : t;

        // cell-warp early loads (independent of everything below)
        float4 gxa, gxb, gxc, gxd;
        float mt = 0.f;
        if (tid < 32) {
            const float* gp = gates2 + (((size_t)s * 64 + cb) * 32 + tid) * 16;
            gxa = *(const float4*)(gp + 0);
            gxb = *(const float4*)(gp + 4);
            gxc = *(const float4*)(gp + 8);
            gxd = *(const float4*)(gp + 12);
            mt  = __ldg(mask + tid * SS + s);
        }

        if (t > 0) {
            if (tid < 64) {
                const int* p = fl_my + tid;
                while (ld_acquire_gpu(p) < t) { }   // pure spin
            }
            __syncthreads();

            // stage h(t-1) into swizzled smem: src [b][k] row-major float4
            const float4* src = (const float4*)hx + ((size_t)dir * 2 + ((t - 1) & 1)) * 2048;
            for (int q = tid; q < 2048; q += 256) {
                int b  = q >> 6;
                int k4 = q & 63;
                int kss = k4 >> 3, j = k4 & 7;
                float4 v = __ldcg(src + q);
                sh_h4[b * 66 + kss * 8 + ((j + kss) & 7)] = v;
            }
            __syncthreads();

            // ---- hGEMM: acc[4b][4r] over k-slice, packed pairs ----
            ull acc[4][4];
#pragma unroll
            for (int i = 0; i < 4; ++i)
#pragma unroll
                for (int r = 0; r < 4; ++r) acc[i][r] = 0ull;

#pragma unroll
            for (int k2 = 0; k2 < 16; ++k2) {
                const int co = (((k2 >> 1) + ks) & 7) * 2 + (k2 & 1);
#pragma unroll
                for (int i = 0; i < 4; ++i) {
                    const ull* hp = (const ull*)&sh_h4[(bg * 4 + i) * 66 + ks * 8];
                    ull h = hp[co];
#pragma unroll
                    for (int r = 0; r < 4; ++r)
                        acc[i][r] = ffma2(h, w[r][k2], acc[i][r]);
                }
            }

            // horizontal add -> floats, then 3-round float butterfly over ks
            float g[4][4];
#pragma unroll
            for (int i = 0; i < 4; ++i)
#pragma unroll
                for (int r = 0; r < 4; ++r) {
                    float2 u = unpack2(acc[i][r]);
                    g[i][r] = u.x + u.y;
                }
#pragma unroll
            for (int d = 1; d < 8; d <<= 1) {
#pragma unroll
                for (int i = 0; i < 4; ++i)
#pragma unroll
                    for (int r = 0; r < 4; ++r)
                        g[i][r] += __shfl_xor_sync(0xffffffffu, g[i][r], d);
            }
            if (ks == 0) {
#pragma unroll
                for (int i = 0; i < 4; ++i)
#pragma unroll
                    for (int r = 0; r < 4; ++r)
                        sh_g[(bg * 4 + i) * 20 + rg * 4 + r] = g[i][r];
            }
        } else {
            if (tid < 32) {
#pragma unroll
                for (int r = 0; r < 16; ++r) sh_g[tid * 20 + r] = 0.f;
            }
        }
        __syncthreads();

        // ---- cell (32 threads, one batch each, 4 units) ----
        if (tid < 32) {
            const float* gh = &sh_g[tid * 20];
            float4 hn4, cn4;
            float* hnp = &hn4.x;
            float* cnp = &cn4.x;
            float* csp = &c4.x;
            const float* gxi = &gxa.x;
            const float* gxf = &gxb.x;
            const float* gxg = &gxc.x;
            const float* gxo = &gxd.x;
#pragma unroll
            for (int u = 0; u < 4; ++u) {
                float ig = sigm_f(gxi[u] + gh[0  + u]);
                float fg = sigm_f(gxf[u] + gh[4  + u]);
                float gv = tanh_f(gxg[u] + gh[8  + u]);
                float og = sigm_f(gxo[u] + gh[12 + u]);
                float cn = fg * csp[u] + ig * gv;
                float hn = og * tanh_f(cn);
                hn *= mt;            // + h0*(1-mt), h0 == 0
                cn *= mt;            // + c0*(1-mt), c0 == 0
                csp[u] = cn;
                hnp[u] = hn;
                cnp[u] = cn;
            }
            // exchange buffer (critical path): [b][k] float4 index b*64+cb
            ((float4*)hx)[((size_t)dir * 2 + (t & 1)) * 2048 + tid * 64 + cb] = hn4;
            // layer output (off critical path)
            size_t orow = out_bs ? ((size_t)tid * SS + s)
                                 : ((size_t)s * BB + tid);
            *(float4*)&xout[orow * H2 + dir * HH + u0] = hn4;
            if (t == SS - 1) {
                *(float4*)&hn_out[tid * H2 + dir * HH + u0] = hn4;
                *(float4*)&cn_out[tid * H2 + dir * HH + u0] = cn4;
            }
        }
        __syncthreads();   // h stores happen-before the releases
        if (tid < 64) {
            st_release_gpu(fl_base + tid * 64 + cb, t + 1);
        }
    }
}

// --------------------------------------------------------------------------
extern "C" void kernel_launch(void* const* d_in, const int* in_sizes, int n_in,
                              void* d_out, int out_size)
{
    const float* inputs  = (const float*)d_in[0];
    const float* mask    = (const float*)d_in[1];
    const float* l0f_Wih = (const float*)d_in[2];
    const float* l0f_Whh = (const float*)d_in[3];
    const float* l0f_bih = (const float*)d_in[4];
    const float* l0f_bhh = (const float*)d_in[5];
    const float* l0b_Wih = (const float*)d_in[6];
    const float* l0b_Whh = (const float*)d_in[7];
    const float* l0b_bih = (const float*)d_in[8];
    const float* l0b_bhh = (const float*)d_in[9];
    const float* l1f_Wih = (const float*)d_in[10];
    const float* l1f_Whh = (const float*)d_in[11];
    const float* l1f_bih = (const float*)d_in[12];
    const float* l1f_bhh = (const float*)d_in[13];
    const float* l1b_Wih = (const float*)d_in[14];
    const float* l1b_Whh = (const float*)d_in[15];
    const float* l1b_bih = (const float*)d_in[16];
    const float* l1b_bhh = (const float*)d_in[17];
    float* out = (float*)d_out;

    float *p_gf, *p_gb, *p_x, *p_hx;
    int *p_fl;
    cudaGetSymbolAddress((void**)&p_gf, g_gates_f);
    cudaGetSymbolAddress((void**)&p_gb, g_gates_b);
    cudaGetSymbolAddress((void**)&p_x,  g_xout);
    cudaGetSymbolAddress((void**)&p_fl, g_flags);
    cudaGetSymbolAddress((void**)&p_hx, g_hx);

    const size_t HN_OFF = (size_t)BB * SS * H2;       // 16777216
    const size_t CN_OFF = HN_OFF + 2 * (size_t)BB * H2;
    float* hn0 = out + HN_OFF;
    float* hn1 = out + HN_OFF + (size_t)BB * H2;
    float* cn0 = out + CN_OFF;
    float* cn1 = out + CN_OFF + (size_t)BB * H2;

    zero_flags_k<<<64, 256>>>();

    dim3 ggrid(G4 / 128, (SS * BB) / 128, 2);   // (8, 256, 2) fwd+bwd merged

    // ---- layer 0 : recurrence output in [S,B,2H] scratch ----
    gates_gemm<<<ggrid, 256>>>(inputs,
                               l0f_Wih, l0f_bih, l0f_bhh,
                               l0b_Wih, l0b_bih, l0b_bhh,
                               p_gf, p_gb, 256, 0);
    lstm_recur<<<128, 256>>>(p_gf, p_gb, l0f_Whh, l0b_Whh, mask,
                             p_x, hn0, cn0, p_fl, p_hx, 0);

    // ---- layer 1 : recurrence writes final [B,S,2H] output directly ----
    gates_gemm<<<ggrid, 256>>>(p_x,
                               l1f_Wih, l1f_bih, l1f_bhh,
                               l1b_Wih, l1b_bih, l1b_bhh,
                               p_gf, p_gb, 512, 1);
    lstm_recur<<<128, 256>>>(p_gf, p_gb, l1f_Whh, l1b_Whh, mask,
                             out, hn1, cn1, p_fl + 2 * 64 * 64, p_hx, 1);
}

// round 16
// speedup vs baseline: 1.3923x; 1.0542x over previous
#include <cuda_runtime.h>
#include <cstdint>

#define BB   32
#define SS   1024
#define HH   256
#define G4   1024   // 4*H
#define H2   512    // 2*H

typedef unsigned long long ull;

// ---------------- f32x2 helpers (Blackwell packed fp32, 2 MAC/inst) -------
__device__ __forceinline__ ull ffma2(ull a, ull b, ull c)
{
    ull d;
    asm("fma.rn.f32x2 %0, %1, %2, %3;" : "=l"(d) : "l"(a), "l"(b), "l"(c));
    return d;
}
__device__ __forceinline__ ull pack_dup(float a)
{
    ull d;
    unsigned u = __float_as_uint(a);
    asm("mov.b64 %0, {%1, %1};" : "=l"(d) : "r"(u));
    return d;
}
__device__ __forceinline__ float2 unpack2(ull v)
{
    unsigned lo, hi;
    asm("mov.b64 {%0, %1}, %2;" : "=r"(lo), "=r"(hi) : "l"(v));
    return make_float2(__uint_as_float(lo), __uint_as_float(hi));
}

// ---------------- scoped release/acquire flag ops -------------------------
__device__ __forceinline__ void st_release_gpu(int* p, int v)
{
    asm volatile("st.release.gpu.global.u32 [%0], %1;" :: "l"(p), "r"(v) : "memory");
}
__device__ __forceinline__ int ld_acquire_gpu(const int* p)
{
    int v;
    asm volatile("ld.acquire.gpu.global.u32 %0, [%1];" : "=r"(v) : "l"(p) : "memory");
    return v;
}

// ------------------------- scratch (device globals; no allocs) -------------
// layer-0 gates, recurrence layout: [s][cb(64)][b(32)][16]
__device__ float g_gates_f[(size_t)SS * BB * G4];   // 128 MB
__device__ float g_gates_b[(size_t)SS * BB * G4];   // 128 MB
// layer-1 gate CONTRIBUTIONS (split-K by direction), same layout:
__device__ float g_c_fa[(size_t)SS * BB * G4];      // l1f, from x_fwd (+bias)
__device__ float g_c_fb[(size_t)SS * BB * G4];      // l1f, from x_bwd
__device__ float g_c_ba[(size_t)SS * BB * G4];      // l1b, from x_fwd (+bias)
__device__ float g_c_bb[(size_t)SS * BB * G4];      // l1b, from x_bwd
__device__ float g_xout [(size_t)SS * BB * H2];     // layer-0 output [s][b][512]
// replicated flags: [layer][dir][consumer(64)][producer(64)]
__device__ int   g_flags [2 * 2 * 64 * 64];
// h exchange: [dir][parity][b(32)][64] float4
__device__ float g_hx    [2 * 2 * 32 * 256];

#define SMRAW_BYTES 36352   // max(rec: 33792+2560, gemm: 2*16*132*4*2)

// --------------------------------------------------------------------------
__global__ void zero_flags_k()
{
    int i = blockIdx.x * blockDim.x + threadIdx.x;
    if (i < 2 * 2 * 64 * 64) g_flags[i] = 0;
}

// --------------------------------------------------------------------------
// Layer-0 x-GEMM (R15, unchanged): 128x128 tiles, f32x2, double-buffered.
__global__ void __launch_bounds__(256) gates_gemm(
    const float* __restrict__ A,
    const float* __restrict__ Wf, const float* __restrict__ bihf, const float* __restrict__ bhhf,
    const float* __restrict__ Wb, const float* __restrict__ bihb, const float* __restrict__ bhhb,
    float* __restrict__ Cf, float* __restrict__ Cb,
    int K, int a_mode)
{
    __shared__ __align__(16) float As[2][16][132];
    __shared__ __align__(16) float Bs[2][16][132];

    const int z = blockIdx.z;
    const float* W   = z ? Wb   : Wf;
    const float* bih = z ? bihb : bihf;
    const float* bhh = z ? bhhb : bhhf;
    float* C2        = z ? Cb   : Cf;

    const int tid = threadIdx.x;
    const int tx = tid & 15;
    const int ty = tid >> 4;
    const int m0 = blockIdx.y * 128;
    const int n0 = blockIdx.x * 128;

    const int lr = tid >> 2;
    const int lc = (tid & 3) << 2;

    const float* arow0;
    const float* arow1;
    {
        int m  = m0 + lr;
        int m2 = m + 64;
        if (a_mode == 0) {
            int s = m >> 5, b = m & 31;
            arow0 = A + ((size_t)b * SS + s) * K;
            s = m2 >> 5; b = m2 & 31;
            arow1 = A + ((size_t)b * SS + s) * K;
        } else {
            arow0 = A + (size_t)m  * K;
            arow1 = A + (size_t)m2 * K;
        }
    }
    const float* wrow0 = W + (size_t)(n0 + lr)      * K;
    const float* wrow1 = W + (size_t)(n0 + lr + 64) * K;

    ull accp[8][4];
#pragma unroll
    for (int i = 0; i < 8; ++i)
#pragma unroll
        for (int j = 0; j < 4; ++j) accp[i][j] = 0ull;

    const int KT = K >> 4;

    float4 a0 = *(const float4*)(arow0 + lc);
    float4 a1 = *(const float4*)(arow1 + lc);
    float4 b0 = *(const float4*)(wrow0 + lc);
    float4 b1 = *(const float4*)(wrow1 + lc);

    for (int kt = 0; kt < KT; ++kt) {
        const int bs = kt & 1;
        As[bs][lc + 0][lr] = a0.x; As[bs][lc + 1][lr] = a0.y;
        As[bs][lc + 2][lr] = a0.z; As[bs][lc + 3][lr] = a0.w;
        As[bs][lc + 0][lr + 64] = a1.x; As[bs][lc + 1][lr + 64] = a1.y;
        As[bs][lc + 2][lr + 64] = a1.z; As[bs][lc + 3][lr + 64] = a1.w;
        Bs[bs][lc + 0][lr] = b0.x; Bs[bs][lc + 1][lr] = b0.y;
        Bs[bs][lc + 2][lr] = b0.z; Bs[bs][lc + 3][lr] = b0.w;
        Bs[bs][lc + 0][lr + 64] = b1.x; Bs[bs][lc + 1][lr + 64] = b1.y;
        Bs[bs][lc + 2][lr + 64] = b1.z; Bs[bs][lc + 3][lr + 64] = b1.w;
        __syncthreads();
        if (kt + 1 < KT) {
            int k0 = (kt + 1) << 4;
            a0 = *(const float4*)(arow0 + k0 + lc);
            a1 = *(const float4*)(arow1 + k0 + lc);
            b0 = *(const float4*)(wrow0 + k0 + lc);
            b1 = *(const float4*)(wrow1 + k0 + lc);
        }
#pragma unroll
        for (int k = 0; k < 16; ++k) {
            float4 af0 = *(const float4*)&As[bs][k][ty * 4];
            float4 af1 = *(const float4*)&As[bs][k][64 + ty * 4];
            ulonglong2 bv0 = *(const ulonglong2*)&Bs[bs][k][tx * 4];
            ulonglong2 bv1 = *(const ulonglong2*)&Bs[bs][k][64 + tx * 4];
            ull bp[4] = {bv0.x, bv0.y, bv1.x, bv1.y};
            float a_[8] = {af0.x, af0.y, af0.z, af0.w, af1.x, af1.y, af1.z, af1.w};
#pragma unroll
            for (int i = 0; i < 8; ++i) {
                ull ad = pack_dup(a_[i]);
#pragma unroll
                for (int j = 0; j < 4; ++j)
                    accp[i][j] = ffma2(ad, bp[j], accp[i][j]);
            }
        }
    }

#pragma unroll
    for (int qi = 0; qi < 2; ++qi) {
#pragma unroll
        for (int i = 0; i < 4; ++i) {
            int m = m0 + qi * 64 + ty * 4 + i;
            int s = m >> 5, b = m & 31;
#pragma unroll
            for (int qj = 0; qj < 2; ++qj) {
                int n = n0 + qj * 64 + tx * 4;
                float2 p0 = unpack2(accp[qi * 4 + i][qj * 2 + 0]);
                float2 p1 = unpack2(accp[qi * 4 + i][qj * 2 + 1]);
                float4 v;
                v.x = p0.x + bih[n + 0] + bhh[n + 0];
                v.y = p0.y + bih[n + 1] + bhh[n + 1];
                v.z = p1.x + bih[n + 2] + bhh[n + 2];
                v.w = p1.y + bih[n + 3] + bhh[n + 3];
                int g  = n >> 8;
                int ub = (n & 255) >> 2;
                *(float4*)&C2[(((size_t)s * 64 + ub) * 32 + b) * 16 + g * 4] = v;
            }
        }
    }
}

// --------------------------------------------------------------------------
__device__ __forceinline__ float sigm_f(float x)
{
    float e = __expf(-x);
    return __fdividef(1.f, 1.f + e);
}
__device__ __forceinline__ float tanh_f(float x)
{
    float xc = fminf(fmaxf(x, -30.f), 30.f);
    float e = __expf(-2.f * xc);
    return __fdividef(1.f - e, 1.f + e);
}

// --------------------------------------------------------------------------
// Recurrence body (R15 structure verbatim). DUAL=1 adds a second gate-
// contribution buffer pair (layer-1: fwd-half + bwd-half contributions).
template <int DUAL>
__device__ __forceinline__ void rec_body(
    char* smraw, int bid,
    const float* gA, const float* gB,       // primary gates (dir 0 / dir 1)
    const float* gA2, const float* gB2,     // secondary (DUAL only)
    const float* WhhF, const float* WhhB,
    const float* mask, float* xout,
    float* hn_out, float* cn_out,
    int* flags, float* hx, int out_bs)
{
    float4* sh_h4 = (float4*)smraw;                 // 32*66
    float*  sh_g  = (float*)(smraw + 32 * 66 * 16); // 32*20

    const int tid  = threadIdx.x;
    const int dir  = bid >> 6;
    const int cb   = bid & 63;
    const int u0   = cb * 4;
    const int bg   = tid >> 5;
    const int lane = tid & 31;
    const int rg   = lane >> 3;
    const int ks   = lane & 7;

    const float* g1 = dir ? gB  : gA;
    const float* g2 = dir ? gB2 : gA2;
    const float* Whh = dir ? WhhB : WhhF;
    int* fl_my   = flags + (dir * 64 + cb) * 64;
    int* fl_base = flags + dir * 64 * 64;

    ull w[4][16];
#pragma unroll
    for (int r = 0; r < 4; ++r) {
        const float* wr = Whh + (size_t)(rg * HH + u0 + r) * HH + ks * 32;
#pragma unroll
        for (int f = 0; f < 8; ++f) {
            ulonglong2 v = *(const ulonglong2*)(wr + f * 4);
            w[r][f * 2 + 0] = v.x;
            w[r][f * 2 + 1] = v.y;
        }
    }

    float4 c4 = make_float4(0.f, 0.f, 0.f, 0.f);

    for (int t = 0; t < SS; ++t) {
        const int s = dir ? (SS - 1 - t) : t;

        float4 gxa, gxb, gxc, gxd;
        float mt = 0.f;
        if (tid < 32) {
            const size_t go = (((size_t)s * 64 + cb) * 32 + tid) * 16;
            const float* gp = g1 + go;
            gxa = *(const float4*)(gp + 0);
            gxb = *(const float4*)(gp + 4);
            gxc = *(const float4*)(gp + 8);
            gxd = *(const float4*)(gp + 12);
            if (DUAL) {
                const float* gq = g2 + go;
                float4 qa = *(const float4*)(gq + 0);
                float4 qb = *(const float4*)(gq + 4);
                float4 qc = *(const float4*)(gq + 8);
                float4 qd = *(const float4*)(gq + 12);
                gxa.x += qa.x; gxa.y += qa.y; gxa.z += qa.z; gxa.w += qa.w;
                gxb.x += qb.x; gxb.y += qb.y; gxb.z += qb.z; gxb.w += qb.w;
                gxc.x += qc.x; gxc.y += qc.y; gxc.z += qc.z; gxc.w += qc.w;
                gxd.x += qd.x; gxd.y += qd.y; gxd.z += qd.z; gxd.w += qd.w;
            }
            mt = __ldg(mask + tid * SS + s);
        }

        if (t > 0) {
            if (tid < 64) {
                const int* p = fl_my + tid;
                while (ld_acquire_gpu(p) < t) { }
            }
            __syncthreads();

            const float4* src = (const float4*)hx + ((size_t)dir * 2 + ((t - 1) & 1)) * 2048;
            for (int q = tid; q < 2048; q += 256) {
                int b  = q >> 6;
                int k4 = q & 63;
                int kss = k4 >> 3, j = k4 & 7;
                float4 v = __ldcg(src + q);
                sh_h4[b * 66 + kss * 8 + ((j + kss) & 7)] = v;
            }
            __syncthreads();

            ull acc[4][4];
#pragma unroll
            for (int i = 0; i < 4; ++i)
#pragma unroll
                for (int r = 0; r < 4; ++r) acc[i][r] = 0ull;

#pragma unroll
            for (int k2 = 0; k2 < 16; ++k2) {
                const int co = (((k2 >> 1) + ks) & 7) * 2 + (k2 & 1);
#pragma unroll
                for (int i = 0; i < 4; ++i) {
                    const ull* hp = (const ull*)&sh_h4[(bg * 4 + i) * 66 + ks * 8];
                    ull h = hp[co];
#pragma unroll
                    for (int r = 0; r < 4; ++r)
                        acc[i][r] = ffma2(h, w[r][k2], acc[i][r]);
                }
            }

            float g[4][4];
#pragma unroll
            for (int i = 0; i < 4; ++i)
#pragma unroll
                for (int r = 0; r < 4; ++r) {
                    float2 u = unpack2(acc[i][r]);
                    g[i][r] = u.x + u.y;
                }
#pragma unroll
            for (int d = 1; d < 8; d <<= 1) {
#pragma unroll
                for (int i = 0; i < 4; ++i)
#pragma unroll
                    for (int r = 0; r < 4; ++r)
                        g[i][r] += __shfl_xor_sync(0xffffffffu, g[i][r], d);
            }
            if (ks == 0) {
#pragma unroll
                for (int i = 0; i < 4; ++i)
#pragma unroll
                    for (int r = 0; r < 4; ++r)
                        sh_g[(bg * 4 + i) * 20 + rg * 4 + r] = g[i][r];
            }
        } else {
            if (tid < 32) {
#pragma unroll
                for (int r = 0; r < 16; ++r) sh_g[tid * 20 + r] = 0.f;
            }
        }
        __syncthreads();

        if (tid < 32) {
            const float* gh = &sh_g[tid * 20];
            float4 hn4, cn4;
            float* hnp = &hn4.x;
            float* cnp = &cn4.x;
            float* csp = &c4.x;
            const float* gxi = &gxa.x;
            const float* gxf = &gxb.x;
            const float* gxg = &gxc.x;
            const float* gxo = &gxd.x;
#pragma unroll
            for (int u = 0; u < 4; ++u) {
                float ig = sigm_f(gxi[u] + gh[0  + u]);
                float fg = sigm_f(gxf[u] + gh[4  + u]);
                float gv = tanh_f(gxg[u] + gh[8  + u]);
                float og = sigm_f(gxo[u] + gh[12 + u]);
                float cn = fg * csp[u] + ig * gv;
                float hn = og * tanh_f(cn);
                hn *= mt;
                cn *= mt;
                csp[u] = cn;
                hnp[u] = hn;
                cnp[u] = cn;
            }
            ((float4*)hx)[((size_t)dir * 2 + (t & 1)) * 2048 + tid * 64 + cb] = hn4;
            size_t orow = out_bs ? ((size_t)tid * SS + s)
                                 : ((size_t)s * BB + tid);
            *(float4*)&xout[orow * H2 + dir * HH + u0] = hn4;
            if (t == SS - 1) {
                *(float4*)&hn_out[tid * H2 + dir * HH + u0] = hn4;
                *(float4*)&cn_out[tid * H2 + dir * HH + u0] = cn4;
            }
        }
        __syncthreads();
        if (tid < 64) {
            st_release_gpu(fl_base + tid * 64 + cb, t + 1);
        }
    }
}

// --------------------------------------------------------------------------
// Layer-1 contribution GEMM CTA: waits (acquire) on layer-0 flags for its
// 4 s-rows in ONE direction, then computes a 128x128 K=256 tile of
// gates1 contribution. half=0: x_fwd cols (+bias); half=1: x_bwd cols.
__device__ void gemm1_body(
    char* smraw, int gid,
    const float* xout, const int* flags0,
    const float* Wf, const float* bihf, const float* bhhf,
    const float* Wb, const float* bihb, const float* bhhb,
    float* c_fa, float* c_fb, float* c_ba, float* c_bb)
{
    float* As = (float*)smraw;           // [2][16][132]
    float* Bs = As + 2 * 16 * 132;

    // id order == readiness order: [ny_rank(256)][z(2)][half(2)][nx(8)]
    const int nyr  = gid >> 5;
    const int z    = (gid >> 4) & 1;
    const int half = (gid >> 3) & 1;
    const int nx   = gid & 7;
    const int ny   = half ? (255 - nyr) : nyr;

    const int tid = threadIdx.x;
    const int thr = half ? (1024 - 4 * ny) : (4 * ny + 4);
    const int* prow = flags0 + half * 64 * 64 + (gid & 63) * 64;
    if (tid < 64) {
        const int* p = prow + tid;
        if (ld_acquire_gpu(p) < thr) {
            while (ld_acquire_gpu(p) < thr) { __nanosleep(1024); }
        }
    }
    __syncthreads();

    const float* W   = z ? Wb   : Wf;
    const float* bih = z ? bihb : bihf;
    const float* bhh = z ? bhhb : bhhf;
    float* C2 = z ? (half ? c_bb : c_ba) : (half ? c_fb : c_fa);

    const int m0 = ny * 128;
    const int n0 = nx * 128;
    const int koff = half * 256;

    const int tx = tid & 15;
    const int ty = tid >> 4;
    const int lr = tid >> 2;
    const int lc = (tid & 3) << 2;

    const float* arow0 = xout + (size_t)(m0 + lr)      * H2 + koff;
    const float* arow1 = xout + (size_t)(m0 + lr + 64) * H2 + koff;
    const float* wrow0 = W + (size_t)(n0 + lr)      * H2 + koff;
    const float* wrow1 = W + (size_t)(n0 + lr + 64) * H2 + koff;

    ull accp[8][4];
#pragma unroll
    for (int i = 0; i < 8; ++i)
#pragma unroll
        for (int j = 0; j < 4; ++j) accp[i][j] = 0ull;

    const int KT = 16;   // K = 256

    float4 a0 = __ldcg((const float4*)(arow0 + lc));
    float4 a1 = __ldcg((const float4*)(arow1 + lc));
    float4 b0 = *(const float4*)(wrow0 + lc);
    float4 b1 = *(const float4*)(wrow1 + lc);

    for (int kt = 0; kt < KT; ++kt) {
        float* Ab = As + (kt & 1) * 16 * 132;
        float* Bb = Bs + (kt & 1) * 16 * 132;
        Ab[(lc + 0) * 132 + lr] = a0.x; Ab[(lc + 1) * 132 + lr] = a0.y;
        Ab[(lc + 2) * 132 + lr] = a0.z; Ab[(lc + 3) * 132 + lr] = a0.w;
        Ab[(lc + 0) * 132 + lr + 64] = a1.x; Ab[(lc + 1) * 132 + lr + 64] = a1.y;
        Ab[(lc + 2) * 132 + lr + 64] = a1.z; Ab[(lc + 3) * 132 + lr + 64] = a1.w;
        Bb[(lc + 0) * 132 + lr] = b0.x; Bb[(lc + 1) * 132 + lr] = b0.y;
        Bb[(lc + 2) * 132 + lr] = b0.z; Bb[(lc + 3) * 132 + lr] = b0.w;
        Bb[(lc + 0) * 132 + lr + 64] = b1.x; Bb[(lc + 1) * 132 + lr + 64] = b1.y;
        Bb[(lc + 2) * 132 + lr + 64] = b1.z; Bb[(lc + 3) * 132 + lr + 64] = b1.w;
        __syncthreads();
        if (kt + 1 < KT) {
            int k0 = (kt + 1) << 4;
            a0 = __ldcg((const float4*)(arow0 + k0 + lc));
            a1 = __ldcg((const float4*)(arow1 + k0 + lc));
            b0 = *(const float4*)(wrow0 + k0 + lc);
            b1 = *(const float4*)(wrow1 + k0 + lc);
        }
#pragma unroll
        for (int k = 0; k < 16; ++k) {
            float4 af0 = *(const float4*)&Ab[k * 132 + ty * 4];
            float4 af1 = *(const float4*)&Ab[k * 132 + 64 + ty * 4];
            ulonglong2 bv0 = *(const ulonglong2*)&Bb[k * 132 + tx * 4];
            ulonglong2 bv1 = *(const ulonglong2*)&Bb[k * 132 + 64 + tx * 4];
            ull bp[4] = {bv0.x, bv0.y, bv1.x, bv1.y};
            float a_[8] = {af0.x, af0.y, af0.z, af0.w, af1.x, af1.y, af1.z, af1.w};
#pragma unroll
            for (int i = 0; i < 8; ++i) {
                ull ad = pack_dup(a_[i]);
#pragma unroll
                for (int j = 0; j < 4; ++j)
                    accp[i][j] = ffma2(ad, bp[j], accp[i][j]);
            }
        }
    }

#pragma unroll
    for (int qi = 0; qi < 2; ++qi) {
#pragma unroll
        for (int i = 0; i < 4; ++i) {
            int m = m0 + qi * 64 + ty * 4 + i;
            int s = m >> 5, b = m & 31;
#pragma unroll
            for (int qj = 0; qj < 2; ++qj) {
                int n = n0 + qj * 64 + tx * 4;
                float2 p0 = unpack2(accp[qi * 4 + i][qj * 2 + 0]);
                float2 p1 = unpack2(accp[qi * 4 + i][qj * 2 + 1]);
                float4 v;
                if (half == 0) {
                    v.x = p0.x + bih[n + 0] + bhh[n + 0];
                    v.y = p0.y + bih[n + 1] + bhh[n + 1];
                    v.z = p1.x + bih[n + 2] + bhh[n + 2];
                    v.w = p1.y + bih[n + 3] + bhh[n + 3];
                } else {
                    v.x = p0.x; v.y = p0.y; v.z = p1.x; v.w = p1.y;
                }
                int g  = n >> 8;
                int ub = (n & 255) >> 2;
                *(float4*)&C2[(((size_t)s * 64 + ub) * 32 + b) * 16 + g * 4] = v;
            }
        }
    }
}

// --------------------------------------------------------------------------
// Mega kernel: blocks 0..127 = layer-0 recurrence (wave-1 resident);
// blocks 128.. = layer-1 contribution GEMMs, flag-gated on rec-0 progress.
__global__ void __launch_bounds__(256) mega_rec0_gemm1(
    const float* __restrict__ g0f, const float* __restrict__ g0b,
    const float* __restrict__ l0f_Whh, const float* __restrict__ l0b_Whh,
    const float* __restrict__ mask,
    float* __restrict__ xout, float* __restrict__ hn0, float* __restrict__ cn0,
    int* __restrict__ flags0, float* __restrict__ hx,
    const float* __restrict__ l1f_Wih, const float* __restrict__ l1f_bih, const float* __restrict__ l1f_bhh,
    const float* __restrict__ l1b_Wih, const float* __restrict__ l1b_bih, const float* __restrict__ l1b_bhh,
    float* __restrict__ c_fa, float* __restrict__ c_fb,
    float* __restrict__ c_ba, float* __restrict__ c_bb)
{
    __shared__ __align__(16) char smraw[SMRAW_BYTES];
    if (blockIdx.x < 128) {
        rec_body<0>(smraw, blockIdx.x, g0f, g0b, nullptr, nullptr,
                    l0f_Whh, l0b_Whh, mask, xout, hn0, cn0, flags0, hx, 0);
    } else {
        gemm1_body(smraw, blockIdx.x - 128, xout, flags0,
                   l1f_Wih, l1f_bih, l1f_bhh,
                   l1b_Wih, l1b_bih, l1b_bhh,
                   c_fa, c_fb, c_ba, c_bb);
    }
}

// --------------------------------------------------------------------------
// Layer-1 recurrence: reads summed contributions (two buffers per dir).
__global__ void __launch_bounds__(256) lstm_recur1(
    const float* __restrict__ c_fa, const float* __restrict__ c_ba,
    const float* __restrict__ c_fb, const float* __restrict__ c_bb,
    const float* __restrict__ l1f_Whh, const float* __restrict__ l1b_Whh,
    const float* __restrict__ mask,
    float* __restrict__ out, float* __restrict__ hn1, float* __restrict__ cn1,
    int* __restrict__ flags1, float* __restrict__ hx)
{
    __shared__ __align__(16) char smraw[SMRAW_BYTES];
    rec_body<1>(smraw, blockIdx.x, c_fa, c_ba, c_fb, c_bb,
                l1f_Whh, l1b_Whh, mask, out, hn1, cn1, flags1, hx, 1);
}

// --------------------------------------------------------------------------
extern "C" void kernel_launch(void* const* d_in, const int* in_sizes, int n_in,
                              void* d_out, int out_size)
{
    const float* inputs  = (const float*)d_in[0];
    const float* mask    = (const float*)d_in[1];
    const float* l0f_Wih = (const float*)d_in[2];
    const float* l0f_Whh = (const float*)d_in[3];
    const float* l0f_bih = (const float*)d_in[4];
    const float* l0f_bhh = (const float*)d_in[5];
    const float* l0b_Wih = (const float*)d_in[6];
    const float* l0b_Whh = (const float*)d_in[7];
    const float* l0b_bih = (const float*)d_in[8];
    const float* l0b_bhh = (const float*)d_in[9];
    const float* l1f_Wih = (const float*)d_in[10];
    const float* l1f_Whh = (const float*)d_in[11];
    const float* l1f_bih = (const float*)d_in[12];
    const float* l1f_bhh = (const float*)d_in[13];
    const float* l1b_Wih = (const float*)d_in[14];
    const float* l1b_Whh = (const float*)d_in[15];
    const float* l1b_bih = (const float*)d_in[16];
    const float* l1b_bhh = (const float*)d_in[17];
    float* out = (float*)d_out;

    float *p_gf, *p_gb, *p_x, *p_hx, *p_cfa, *p_cfb, *p_cba, *p_cbb;
    int *p_fl;
    cudaGetSymbolAddress((void**)&p_gf,  g_gates_f);
    cudaGetSymbolAddress((void**)&p_gb,  g_gates_b);
    cudaGetSymbolAddress((void**)&p_x,   g_xout);
    cudaGetSymbolAddress((void**)&p_fl,  g_flags);
    cudaGetSymbolAddress((void**)&p_hx,  g_hx);
    cudaGetSymbolAddress((void**)&p_cfa, g_c_fa);
    cudaGetSymbolAddress((void**)&p_cfb, g_c_fb);
    cudaGetSymbolAddress((void**)&p_cba, g_c_ba);
    cudaGetSymbolAddress((void**)&p_cbb, g_c_bb);

    const size_t HN_OFF = (size_t)BB * SS * H2;       // 16777216
    const size_t CN_OFF = HN_OFF + 2 * (size_t)BB * H2;
    float* hn0 = out + HN_OFF;
    float* hn1 = out + HN_OFF + (size_t)BB * H2;
    float* cn0 = out + CN_OFF;
    float* cn1 = out + CN_OFF + (size_t)BB * H2;

    zero_flags_k<<<64, 256>>>();

    // layer-0 x-GEMMs (fwd+bwd merged via grid.z)
    dim3 ggrid(G4 / 128, (SS * BB) / 128, 2);
    gates_gemm<<<ggrid, 256>>>(inputs,
                               l0f_Wih, l0f_bih, l0f_bhh,
                               l0b_Wih, l0b_bih, l0b_bhh,
                               p_gf, p_gb, 256, 0);

    // mega: layer-0 recurrence + flag-gated layer-1 contribution GEMMs
    mega_rec0_gemm1<<<128 + 8192, 256>>>(
        p_gf, p_gb, l0f_Whh, l0b_Whh, mask,
        p_x, hn0, cn0, p_fl, p_hx,
        l1f_Wih, l1f_bih, l1f_bhh,
        l1b_Wih, l1b_bih, l1b_bhh,
        p_cfa, p_cfb, p_cba, p_cbb);

    // layer-1 recurrence: writes final [B,S,2H] output directly
    lstm_recur1<<<128, 256>>>(p_cfa, p_cba, p_cfb, p_cbb,
                              l1f_Whh, l1b_Whh, mask,
                              out, hn1, cn1, p_fl + 2 * 64 * 64, p_hx);
}